// round 14
// baseline (speedup 1.0000x reference)
#include <cuda_runtime.h>
#include <math.h>
#include <stdint.h>

#define Bn 2
#define C 64
#define H 256
#define W 256
#define S (H*W)
#define HEADS 4
#define HD 16

#define NT6 43           // F(6x6) tiles per dim: 43*6 = 258 = ext grid exactly
#define NTT6 (NT6*NT6)   // 1849 tiles
#define TS6 1920         // tile stride (15*128)
#define NBLK6 15         // gemm 128-tile blocks per (b,f)
#define NF6 64           // frequencies (8x8)
#define GRV 258          // valid ext-grid rows/cols
#define GP 260           // winG row stride
#define NTYG6 8          // in-transform: groups of 6 ty rows (covers 48>=43)
#define NOB 15           // out-transform: 128-tile chunks per plane (15*128>=1849)

// Scratch (device globals -- no allocations allowed; zero-initialized)
__device__ float g_conv[Bn*C*S];
__device__ float g_gram[Bn*HEADS*HD*HD];
__device__ float g_qn2[Bn*HEADS*HD];
__device__ float g_kn2[Bn*HEADS*HD];
__device__ __align__(16) float g_U[NF6*64*64];       // [f][ci][co]  4MB
__device__ __align__(16) float g_V[Bn*NF6*64*TS6];   // [b][f][ci][t] ~63MB
__device__ __align__(16) float g_M[Bn*NF6*64*TS6];   // [b][f][co][t] ~63MB
__device__ __align__(16) float g_winG[Bn*64*GP*GP];

// ---------------------------------------------------------------------------
// B^T (F(6,3), points 0,±1,±2,±1/2) applied to 8-vector.
__device__ __forceinline__ void bt8(const float* d, float* t) {
    t[0] =  d[0] - 5.25f*d[2] + 5.25f*d[4] - d[6];
    t[1] =  d[1] + d[2] - 4.25f*(d[3] + d[4]) + d[5] + d[6];
    t[2] = -d[1] + d[2] + 4.25f*(d[3] - d[4]) - d[5] + d[6];
    t[3] =  0.5f*d[1] + 0.25f*d[2] - 2.5f*d[3] - 1.25f*d[4] + 2.f*d[5] + d[6];
    t[4] = -0.5f*d[1] + 0.25f*d[2] + 2.5f*d[3] - 1.25f*d[4] - 2.f*d[5] + d[6];
    t[5] =  2.f*d[1] + 4.f*d[2] - 2.5f*d[3] - 5.f*d[4] + 0.5f*d[5] + d[6];
    t[6] = -2.f*d[1] + 4.f*d[2] + 2.5f*d[3] - 5.f*d[4] - 0.5f*d[5] + d[6];
    t[7] = -d[1] + 5.25f*d[3] - 5.25f*d[5] + d[7];
}
// G (8x3) applied to 3-vector.
__device__ __forceinline__ void g8(float g0, float g1, float g2, float* u) {
    u[0] = g0;
    u[1] = (-2.f/9.f)*(g0 + g1 + g2);
    u[2] = (-2.f/9.f)*(g0 - g1 + g2);
    u[3] = (1.f/90.f)*g0 + (1.f/45.f)*g1 + (2.f/45.f)*g2;
    u[4] = (1.f/90.f)*g0 - (1.f/45.f)*g1 + (2.f/45.f)*g2;
    u[5] = (32.f/45.f)*g0 + (16.f/45.f)*g1 + (8.f/45.f)*g2;
    u[6] = (32.f/45.f)*g0 - (16.f/45.f)*g1 + (8.f/45.f)*g2;
    u[7] = g2;
}
// A^T (6x8) applied to 8-vector.
__device__ __forceinline__ void at6(const float* m, float* y) {
    float p12 = m[1]+m[2], m12 = m[1]-m[2];
    float p34 = m[3]+m[4], m34 = m[3]-m[4];
    float p56 = m[5]+m[6], m56 = m[5]-m[6];
    y[0] = m[0] + p12 + p34 + p56;
    y[1] = m12 + 2.f*m34 + 0.5f*m56;
    y[2] = p12 + 4.f*p34 + 0.25f*p56;
    y[3] = m12 + 8.f*m34 + 0.125f*m56;
    y[4] = p12 + 16.f*p34 + 0.0625f*p56;
    y[5] = m12 + 32.f*m34 + 0.03125f*m56 + m[7];
}

// ---------------------------------------------------------------------------
// Prep: U = G g G^T (8x8 per (ci,co)); zero gram accumulators.
__global__ void prep_kernel(const float* __restrict__ weight) {
    int t = blockIdx.x*256 + threadIdx.x;        // 0..4095
    if (t < 4096) {
        int co = t & 63, ci = t >> 6;
        float g[3][3];
        #pragma unroll
        for (int k = 0; k < 9; k++) g[k/3][k%3] = weight[(co*C + ci)*9 + k];
        float q[8][3];
        #pragma unroll
        for (int c = 0; c < 3; c++) {
            float col[8];
            g8(g[0][c], g[1][c], g[2][c], col);
            #pragma unroll
            for (int r = 0; r < 8; r++) q[r][c] = col[r];
        }
        #pragma unroll
        for (int r = 0; r < 8; r++) {
            float ur[8];
            g8(q[r][0], q[r][1], q[r][2], ur);
            #pragma unroll
            for (int c = 0; c < 8; c++)
                g_U[(r*8+c)*4096 + ci*64 + co] = ur[c];
        }
    }
    if (blockIdx.x == 0) {
        int tid = threadIdx.x;
        for (int k = tid; k < Bn*HEADS*HD*HD; k += 256) g_gram[k] = 0.f;
        for (int k = tid; k < Bn*HEADS*HD;    k += 256) { g_qn2[k] = 0.f; g_kn2[k] = 0.f; }
    }
}

// ---------------------------------------------------------------------------
// Input transform: V = B^T d B per 8x8 tile (stride 6, zero-padded clone).
// Block = 288 threads: 258 tasks in ONE round (fixes serial tail).
__global__ __launch_bounds__(288) void winograd_in(const float* __restrict__ clone) {
    __shared__ float rows[38][256];
    int z   = blockIdx.x;
    int tyg = z % NTYG6;
    int bc  = z / NTYG6;             // b*64 + ci
    int ci  = bc & 63, b = bc >> 6;
    int tid = threadIdx.x;

    const float* plane = clone + ((size_t)bc << 16);
    int gr0 = 36*tyg - 2;
    for (int i = tid; i < 38*64; i += 288) {
        int r = i >> 6, c4 = i & 63;
        int gr = gr0 + r;
        float4 val = make_float4(0.f,0.f,0.f,0.f);
        if ((unsigned)gr < 256u) val = *(const float4*)(plane + gr*256 + c4*4);
        *(float4*)&rows[r][c4*4] = val;
    }
    __syncthreads();

    int task = tid;
    if (task < 6*NT6) {
        int tyl = task / NT6;            // 0..5
        int tx  = task - tyl*NT6;
        int ty  = 6*tyg + tyl;
        if (ty < NT6) {
            float d[8][8];
            int cbase = 6*tx - 2;
            int rl = 6*tyl;
            #pragma unroll
            for (int jj = 0; jj < 8; jj++) {
                int cc = cbase + jj;
                bool ok = ((unsigned)cc < 256u);
                #pragma unroll
                for (int r = 0; r < 8; r++) d[r][jj] = ok ? rows[rl + r][cc] : 0.f;
            }
            float t[8][8];
            #pragma unroll
            for (int c2 = 0; c2 < 8; c2++) {
                float dc[8], tc[8];
                #pragma unroll
                for (int r = 0; r < 8; r++) dc[r] = d[r][c2];
                bt8(dc, tc);
                #pragma unroll
                for (int r = 0; r < 8; r++) t[r][c2] = tc[r];
            }
            int tlin = ty*NT6 + tx;
            #pragma unroll
            for (int r = 0; r < 8; r++) {
                float vr[8];
                bt8(t[r], vr);
                #pragma unroll
                for (int c2 = 0; c2 < 8; c2++)
                    g_V[((b*NF6 + r*8+c2)*64 + ci)*TS6 + tlin] = vr[c2];
            }
        }
    }
}

// ---------------------------------------------------------------------------
// Per-frequency GEMM, single-stage full-K smem, 8co x 8t thread tile.
__global__ __launch_bounds__(128, 3) void winograd_gemm() {
    __shared__ float Vs[64][128];    // 32 KB
    __shared__ float Us[64][64];     // 16 KB
    int bf = blockIdx.x / NBLK6;     // b*64 + f
    int tc = blockIdx.x % NBLK6;
    int f  = bf & 63;
    int t0 = tc * 128;
    int tid = threadIdx.x;
    int cg = tid >> 4, tg = tid & 15;

    {
        const float* vsrc = &g_V[(size_t)(bf*64)*TS6 + t0];
        #pragma unroll
        for (int i = 0; i < 16; i++) {
            int lin = tid + i*128;
            int r = lin >> 5, c = lin & 31;
            *(float4*)&Vs[r][c*4] = *(const float4*)(vsrc + (size_t)r*TS6 + c*4);
        }
        const float* usrc = &g_U[f*4096];
        #pragma unroll
        for (int i = 0; i < 8; i++) {
            int lin = tid + i*128;
            int r = lin >> 4, c = lin & 15;
            *(float4*)&Us[r][c*4] = *(const float4*)(usrc + r*64 + c*4);
        }
    }
    __syncthreads();

    float acc[8][8];
    #pragma unroll
    for (int i = 0; i < 8; i++)
        #pragma unroll
        for (int j = 0; j < 8; j++) acc[i][j] = 0.f;

    #pragma unroll 4
    for (int cl = 0; cl < 64; cl++) {
        float4 w0 = *(const float4*)&Us[cl][cg*8];
        float4 w1 = *(const float4*)&Us[cl][cg*8 + 4];
        float4 s0 = *(const float4*)&Vs[cl][tg*8];
        float4 s1 = *(const float4*)&Vs[cl][tg*8 + 4];
        float wv[8] = {w0.x, w0.y, w0.z, w0.w, w1.x, w1.y, w1.z, w1.w};
        float sv[8] = {s0.x, s0.y, s0.z, s0.w, s1.x, s1.y, s1.z, s1.w};
        #pragma unroll
        for (int i = 0; i < 8; i++)
            #pragma unroll
            for (int j = 0; j < 8; j++)
                acc[i][j] += wv[i]*sv[j];
    }

    #pragma unroll
    for (int i = 0; i < 8; i++) {
        float* mp = &g_M[(size_t)(bf*64 + cg*8 + i)*TS6 + t0 + tg*8];
        *(float4*)mp       = make_float4(acc[i][0], acc[i][1], acc[i][2], acc[i][3]);
        *(float4*)(mp + 4) = make_float4(acc[i][4], acc[i][5], acc[i][6], acc[i][7]);
    }
}

// ---------------------------------------------------------------------------
// Output transform: Y = A^T m A (6x6 outputs). Flat tlin indexing: one task
// per thread (fixes the 1-active-thread second round of R13).
__global__ __launch_bounds__(128) void winograd_out() {
    int z     = blockIdx.x;
    int chunk = z % NOB;
    int bc    = z / NOB;             // b*64 + co
    int co    = bc & 63, b = bc >> 6;
    int tlin  = chunk*128 + threadIdx.x;
    if (tlin >= NTT6) return;
    int ty = tlin / NT6, tx = tlin - ty*NT6;

    float m[8][8];
    #pragma unroll
    for (int f = 0; f < NF6; f++)
        m[f >> 3][f & 7] = g_M[((b*NF6 + f)*64 + co)*TS6 + tlin];

    float t2[6][8];
    #pragma unroll
    for (int c2 = 0; c2 < 8; c2++) {
        float mc[8], yc[6];
        #pragma unroll
        for (int r = 0; r < 8; r++) mc[r] = m[r][c2];
        at6(mc, yc);
        #pragma unroll
        for (int r = 0; r < 6; r++) t2[r][c2] = yc[r];
    }
    float* gbase = &g_winG[((size_t)bc*GP + 6*ty)*GP + 6*tx];
    #pragma unroll
    for (int r = 0; r < 6; r++) {
        float y[6];
        at6(t2[r], y);
        float* gp = gbase + r*GP;
        *(float2*)(gp)     = make_float2(y[0], y[1]);
        *(float2*)(gp + 2) = make_float2(y[2], y[3]);
        *(float2*)(gp + 4) = make_float2(y[4], y[5]);
    }
}

// ---------------------------------------------------------------------------
// FUSED resample + gram/norms. Per (bh, slice): K tile is gathered directly
// from winG (flow bilinear, clamped-addr x zero-weight for OOB corners) and
// simultaneously written to g_conv for the attention-output pass.
__global__ __launch_bounds__(256) void dots_kernel(
    const float* __restrict__ xg, const float* __restrict__ u,
    const float* __restrict__ v)
{
    __shared__ float qs[16][260];
    __shared__ float ks[16][260];
    __shared__ float s_nq[16], s_nk[16];

    int tid = threadIdx.x;
    int bh  = blockIdx.x >> 5;
    int sl  = blockIdx.x & 31;
    int b   = bh >> 2, hh = bh & 3;
    int i = tid >> 4, j = tid & 15;
    int s0 = sl * 2048;

    if (tid < 16) { s_nq[tid] = 0.f; s_nk[tid] = 0.f; }

    float g = 0.f, nqp = 0.f, nkp = 0.f;
    for (int ch = 0; ch < 8; ++ch) {
        __syncthreads();
        int sbase = s0 + ch*256;
        int px = sbase + tid;                 // this thread's pixel

        // ---- per-pixel gather params (registers only) ----
        int o0, o1, o2, o3;
        float w0, w1, w2, w3;
        {
            int y = px >> 8, x = px & 255;
            float py  = (float)y + v[b*S + px];
            float pxx = (float)x + u[b*S + px];
            float fy = floorf(py), fx = floorf(pxx);
            int y0 = (int)fy, x0 = (int)fx;
            float wy = py - fy, wx = pxx - fx;
            float a00 = (1.f-wy)*(1.f-wx), a01 = (1.f-wy)*wx;
            float a10 = wy*(1.f-wx),       a11 = wy*wx;
            int yc = y0 + 1, xc = x0 + 1;
            bool r0 = ((unsigned)yc     < (unsigned)GRV);
            bool r1 = ((unsigned)(yc+1) < (unsigned)GRV);
            bool c0 = ((unsigned)xc     < (unsigned)GRV);
            bool c1 = ((unsigned)(xc+1) < (unsigned)GRV);
            int ya = min(max(yc,   0), GRV-1), yb = min(max(yc+1, 0), GRV-1);
            int xa = min(max(xc,   0), GRV-1), xb = min(max(xc+1, 0), GRV-1);
            o0 = ya*GP + xa; o1 = ya*GP + xb; o2 = yb*GP + xa; o3 = yb*GP + xb;
            w0 = (r0 && c0) ? a00 : 0.f;
            w1 = (r0 && c1) ? a01 : 0.f;
            w2 = (r1 && c0) ? a10 : 0.f;
            w3 = (r1 && c1) ? a11 : 0.f;
        }

        // ---- stage q tile (float4, coalesced) ----
        #pragma unroll
        for (int e = 0; e < 4; ++e) {
            int lin = tid + e*256;            // 0..1023 float4 units
            int r = lin >> 6, c4 = lin & 63;
            float4 val = *(const float4*)(xg + (size_t)(b*C + hh*HD + r)*S + sbase + c4*4);
            float* dst = &qs[r][c4*4];
            dst[0] = val.x; dst[1] = val.y; dst[2] = val.z; dst[3] = val.w;
        }
        // ---- gather k tile from winG + write conv ----
        #pragma unroll
        for (int e = 0; e < 16; ++e) {
            const float* Gp = g_winG + (size_t)(b*64 + hh*HD + e)*GP*GP;
            float val = w0*__ldg(Gp + o0) + w1*__ldg(Gp + o1)
                      + w2*__ldg(Gp + o2) + w3*__ldg(Gp + o3);
            ks[e][tid] = val;
            g_conv[(size_t)(b*C + hh*HD + e)*S + px] = val;
        }
        __syncthreads();

        #pragma unroll 8
        for (int s = 0; s < 256; s += 4) {
            float4 qv = *(const float4*)&qs[i][s];
            float4 kv = *(const float4*)&ks[j][s];
            g += qv.x*kv.x; g += qv.y*kv.y; g += qv.z*kv.z; g += qv.w*kv.w;
        }
        #pragma unroll 4
        for (int s = j; s < 256; s += 16) { float q0 = qs[i][s]; nqp += q0*q0; }
        #pragma unroll 4
        for (int s = i; s < 256; s += 16) { float k0 = ks[j][s]; nkp += k0*k0; }
    }
    atomicAdd(&g_gram[bh*256 + i*16 + j], g);
    atomicAdd(&s_nq[i], nqp);
    atomicAdd(&s_nk[j], nkp);
    __syncthreads();
    if (tid < 16)       atomicAdd(&g_qn2[bh*16 + tid], s_nq[tid]);
    else if (tid < 32)  atomicAdd(&g_kn2[bh*16 + tid-16], s_nk[tid-16]);
}

// ---------------------------------------------------------------------------
// Fused softmax + out; float2 columns (16 float2 accs) for occupancy.
__global__ __launch_bounds__(256) void out_kernel(float* __restrict__ out,
                                                  const float* __restrict__ temp) {
    __shared__ float s_attn[16][16];
    int tid = threadIdx.x;
    int bh  = blockIdx.x >> 7;     // 128 tiles of 512 px
    int tile = blockIdx.x & 127;
    int b = bh >> 2, hh = bh & 3;

    {
        int i = tid >> 4, j = tid & 15;
        float dq = fmaxf(sqrtf(g_qn2[bh*16 + i]), 1e-12f);
        float dk = fmaxf(sqrtf(g_kn2[bh*16 + j]), 1e-12f);
        float T  = temp[hh];
        float l  = g_gram[bh*256 + i*16 + j] / (dq*dk) * T;
        float m = l;
        #pragma unroll
        for (int off = 8; off > 0; off >>= 1)
            m = fmaxf(m, __shfl_xor_sync(0xffffffffu, m, off, 16));
        float e = expf(l - m);
        float ssum = e;
        #pragma unroll
        for (int off = 8; off > 0; off >>= 1)
            ssum += __shfl_xor_sync(0xffffffffu, ssum, off, 16);
        s_attn[i][j] = e / ssum;
    }
    __syncthreads();

    int s = tile*512 + tid*2;
    float2 acc[16];
    #pragma unroll
    for (int o = 0; o < 16; o++) acc[o] = make_float2(0.f, 0.f);

    #pragma unroll
    for (int d = 0; d < 16; d++) {
        float2 kvv = *(const float2*)&g_conv[(size_t)(b*C + hh*HD + d)*S + s];
        #pragma unroll
        for (int o = 0; o < 16; o++) {
            float a = s_attn[o][d];
            acc[o].x += a*kvv.x; acc[o].y += a*kvv.y;
        }
    }
    #pragma unroll
    for (int o = 0; o < 16; o++)
        *(float2*)&out[(size_t)(b*C + hh*HD + o)*S + s] = acc[o];
}

// ---------------------------------------------------------------------------
extern "C" void kernel_launch(void* const* d_in, const int* in_sizes, int n_in,
                              void* d_out, int out_size) {
    const float* clone  = (const float*)d_in[0];
    const float* xg     = (const float*)d_in[1];
    const float* u      = (const float*)d_in[2];
    const float* v      = (const float*)d_in[3];
    const float* weight = (const float*)d_in[4];
    const float* temp   = (const float*)d_in[5];
    float* out = (float*)d_out;

    prep_kernel<<<16, 256>>>(weight);
    winograd_in<<<Bn*64*NTYG6, 288>>>(clone);
    winograd_gemm<<<Bn*NF6*NBLK6, 128>>>();
    winograd_out<<<Bn*64*NOB, 128>>>();
    dots_kernel<<<Bn*HEADS*32, 256>>>(xg, u, v);
    out_kernel<<<Bn*HEADS*128, 256>>>(out, temp);
}

// round 15
// speedup vs baseline: 1.0509x; 1.0509x over previous
#include <cuda_runtime.h>
#include <math.h>
#include <stdint.h>

#define Bn 2
#define C 64
#define H 256
#define W 256
#define S (H*W)
#define HEADS 4
#define HD 16

#define NT6 43           // F(6x6) tiles per dim: 43*6 = 258 = ext grid exactly
#define NTT6 (NT6*NT6)   // 1849 tiles
#define TS6 1920         // tile stride (15*128)
#define NBLK6 15         // gemm 128-tile blocks per (b,f)
#define NF6 64           // frequencies (8x8)
#define GRV 258          // valid ext-grid rows/cols
#define GP 260           // winG row stride
#define NTYG6 8          // in-transform: groups of 6 ty rows (covers 48>=43)
#define NOB2 8           // out-transform: 256-tile chunks per plane (8*256>=1849)

// Scratch (device globals -- no allocations allowed; zero-initialized)
__device__ float g_conv[Bn*C*S];
__device__ float g_gram[Bn*HEADS*HD*HD];
__device__ float g_qn2[Bn*HEADS*HD];
__device__ float g_kn2[Bn*HEADS*HD];
__device__ __align__(16) float g_U[NF6*64*64];       // [f][ci][co]  4MB
__device__ __align__(16) float g_V[Bn*NF6*64*TS6];   // [b][f][ci][t] ~63MB
__device__ __align__(16) float g_M[Bn*NF6*64*TS6];   // [b][f][co][t] ~63MB
__device__ __align__(16) float g_winG[Bn*64*GP*GP];

// ---------------------------------------------------------------------------
// B^T (F(6,3), points 0,±1,±2,±1/2) applied to 8-vector.
__device__ __forceinline__ void bt8(const float* d, float* t) {
    t[0] =  d[0] - 5.25f*d[2] + 5.25f*d[4] - d[6];
    t[1] =  d[1] + d[2] - 4.25f*(d[3] + d[4]) + d[5] + d[6];
    t[2] = -d[1] + d[2] + 4.25f*(d[3] - d[4]) - d[5] + d[6];
    t[3] =  0.5f*d[1] + 0.25f*d[2] - 2.5f*d[3] - 1.25f*d[4] + 2.f*d[5] + d[6];
    t[4] = -0.5f*d[1] + 0.25f*d[2] + 2.5f*d[3] - 1.25f*d[4] - 2.f*d[5] + d[6];
    t[5] =  2.f*d[1] + 4.f*d[2] - 2.5f*d[3] - 5.f*d[4] + 0.5f*d[5] + d[6];
    t[6] = -2.f*d[1] + 4.f*d[2] + 2.5f*d[3] - 5.f*d[4] - 0.5f*d[5] + d[6];
    t[7] = -d[1] + 5.25f*d[3] - 5.25f*d[5] + d[7];
}
// G (8x3) applied to 3-vector.
__device__ __forceinline__ void g8(float g0, float g1, float g2, float* u) {
    u[0] = g0;
    u[1] = (-2.f/9.f)*(g0 + g1 + g2);
    u[2] = (-2.f/9.f)*(g0 - g1 + g2);
    u[3] = (1.f/90.f)*g0 + (1.f/45.f)*g1 + (2.f/45.f)*g2;
    u[4] = (1.f/90.f)*g0 - (1.f/45.f)*g1 + (2.f/45.f)*g2;
    u[5] = (32.f/45.f)*g0 + (16.f/45.f)*g1 + (8.f/45.f)*g2;
    u[6] = (32.f/45.f)*g0 - (16.f/45.f)*g1 + (8.f/45.f)*g2;
    u[7] = g2;
}
// A^T (6x8) applied to 8-vector.
__device__ __forceinline__ void at6(const float* m, float* y) {
    float p12 = m[1]+m[2], m12 = m[1]-m[2];
    float p34 = m[3]+m[4], m34 = m[3]-m[4];
    float p56 = m[5]+m[6], m56 = m[5]-m[6];
    y[0] = m[0] + p12 + p34 + p56;
    y[1] = m12 + 2.f*m34 + 0.5f*m56;
    y[2] = p12 + 4.f*p34 + 0.25f*p56;
    y[3] = m12 + 8.f*m34 + 0.125f*m56;
    y[4] = p12 + 16.f*p34 + 0.0625f*p56;
    y[5] = m12 + 32.f*m34 + 0.03125f*m56 + m[7];
}

// ---------------------------------------------------------------------------
// Prep: U = G g G^T (8x8 per (ci,co)); zero gram accumulators.
__global__ void prep_kernel(const float* __restrict__ weight) {
    int t = blockIdx.x*256 + threadIdx.x;        // 0..4095
    if (t < 4096) {
        int co = t & 63, ci = t >> 6;
        float g[3][3];
        #pragma unroll
        for (int k = 0; k < 9; k++) g[k/3][k%3] = weight[(co*C + ci)*9 + k];
        float q[8][3];
        #pragma unroll
        for (int c = 0; c < 3; c++) {
            float col[8];
            g8(g[0][c], g[1][c], g[2][c], col);
            #pragma unroll
            for (int r = 0; r < 8; r++) q[r][c] = col[r];
        }
        #pragma unroll
        for (int r = 0; r < 8; r++) {
            float ur[8];
            g8(q[r][0], q[r][1], q[r][2], ur);
            #pragma unroll
            for (int c = 0; c < 8; c++)
                g_U[(r*8+c)*4096 + ci*64 + co] = ur[c];
        }
    }
    if (blockIdx.x == 0) {
        int tid = threadIdx.x;
        for (int k = tid; k < Bn*HEADS*HD*HD; k += 256) g_gram[k] = 0.f;
        for (int k = tid; k < Bn*HEADS*HD;    k += 256) { g_qn2[k] = 0.f; g_kn2[k] = 0.f; }
    }
}

// ---------------------------------------------------------------------------
// Input transform: V = B^T d B per 8x8 tile (stride 6, zero-padded clone).
// Block = 288 threads: 258 tasks in ONE round.
__global__ __launch_bounds__(288) void winograd_in(const float* __restrict__ clone) {
    __shared__ float rows[38][256];
    int z   = blockIdx.x;
    int tyg = z % NTYG6;
    int bc  = z / NTYG6;             // b*64 + ci
    int ci  = bc & 63, b = bc >> 6;
    int tid = threadIdx.x;

    const float* plane = clone + ((size_t)bc << 16);
    int gr0 = 36*tyg - 2;
    for (int i = tid; i < 38*64; i += 288) {
        int r = i >> 6, c4 = i & 63;
        int gr = gr0 + r;
        float4 val = make_float4(0.f,0.f,0.f,0.f);
        if ((unsigned)gr < 256u) val = *(const float4*)(plane + gr*256 + c4*4);
        *(float4*)&rows[r][c4*4] = val;
    }
    __syncthreads();

    int task = tid;
    if (task < 6*NT6) {
        int tyl = task / NT6;            // 0..5
        int tx  = task - tyl*NT6;
        int ty  = 6*tyg + tyl;
        if (ty < NT6) {
            float d[8][8];
            int cbase = 6*tx - 2;
            int rl = 6*tyl;
            #pragma unroll
            for (int jj = 0; jj < 8; jj++) {
                int cc = cbase + jj;
                bool ok = ((unsigned)cc < 256u);
                #pragma unroll
                for (int r = 0; r < 8; r++) d[r][jj] = ok ? rows[rl + r][cc] : 0.f;
            }
            float t[8][8];
            #pragma unroll
            for (int c2 = 0; c2 < 8; c2++) {
                float dc[8], tc[8];
                #pragma unroll
                for (int r = 0; r < 8; r++) dc[r] = d[r][c2];
                bt8(dc, tc);
                #pragma unroll
                for (int r = 0; r < 8; r++) t[r][c2] = tc[r];
            }
            int tlin = ty*NT6 + tx;
            #pragma unroll
            for (int r = 0; r < 8; r++) {
                float vr[8];
                bt8(t[r], vr);
                #pragma unroll
                for (int c2 = 0; c2 < 8; c2++)
                    g_V[((b*NF6 + r*8+c2)*64 + ci)*TS6 + tlin] = vr[c2];
            }
        }
    }
}

// ---------------------------------------------------------------------------
// Per-frequency GEMM, single-stage full-K smem, 8co x 8t thread tile.
__global__ __launch_bounds__(128, 3) void winograd_gemm() {
    __shared__ float Vs[64][128];    // 32 KB
    __shared__ float Us[64][64];     // 16 KB
    int bf = blockIdx.x / NBLK6;     // b*64 + f
    int tc = blockIdx.x % NBLK6;
    int f  = bf & 63;
    int t0 = tc * 128;
    int tid = threadIdx.x;
    int cg = tid >> 4, tg = tid & 15;

    {
        const float* vsrc = &g_V[(size_t)(bf*64)*TS6 + t0];
        #pragma unroll
        for (int i = 0; i < 16; i++) {
            int lin = tid + i*128;
            int r = lin >> 5, c = lin & 31;
            *(float4*)&Vs[r][c*4] = *(const float4*)(vsrc + (size_t)r*TS6 + c*4);
        }
        const float* usrc = &g_U[f*4096];
        #pragma unroll
        for (int i = 0; i < 8; i++) {
            int lin = tid + i*128;
            int r = lin >> 4, c = lin & 15;
            *(float4*)&Us[r][c*4] = *(const float4*)(usrc + r*64 + c*4);
        }
    }
    __syncthreads();

    float acc[8][8];
    #pragma unroll
    for (int i = 0; i < 8; i++)
        #pragma unroll
        for (int j = 0; j < 8; j++) acc[i][j] = 0.f;

    #pragma unroll 4
    for (int cl = 0; cl < 64; cl++) {
        float4 w0 = *(const float4*)&Us[cl][cg*8];
        float4 w1 = *(const float4*)&Us[cl][cg*8 + 4];
        float4 s0 = *(const float4*)&Vs[cl][tg*8];
        float4 s1 = *(const float4*)&Vs[cl][tg*8 + 4];
        float wv[8] = {w0.x, w0.y, w0.z, w0.w, w1.x, w1.y, w1.z, w1.w};
        float sv[8] = {s0.x, s0.y, s0.z, s0.w, s1.x, s1.y, s1.z, s1.w};
        #pragma unroll
        for (int i = 0; i < 8; i++)
            #pragma unroll
            for (int j = 0; j < 8; j++)
                acc[i][j] += wv[i]*sv[j];
    }

    #pragma unroll
    for (int i = 0; i < 8; i++) {
        float* mp = &g_M[(size_t)(bf*64 + cg*8 + i)*TS6 + t0 + tg*8];
        *(float4*)mp       = make_float4(acc[i][0], acc[i][1], acc[i][2], acc[i][3]);
        *(float4*)(mp + 4) = make_float4(acc[i][4], acc[i][5], acc[i][6], acc[i][7]);
    }
}

// ---------------------------------------------------------------------------
// Output transform: Y = A^T m A (6x6 outputs), COLUMN-STREAMED to kill the
// register spills seen in R13/R14 (L1 ~49% = spill traffic): only t2[48]
// plus one 8-value column are live at a time.
__global__ __launch_bounds__(256) void winograd_out() {
    int z     = blockIdx.x;
    int chunk = z % NOB2;
    int bc    = z / NOB2;            // b*64 + co
    int co    = bc & 63, b = bc >> 6;
    int tlin  = chunk*256 + threadIdx.x;
    if (tlin >= NTT6) return;
    int ty = tlin / NT6, tx = tlin - ty*NT6;

    const float* mbase = &g_M[(size_t)(b*NF6*64 + co)*TS6 + tlin];
    float t2[6][8];
    #pragma unroll
    for (int c2 = 0; c2 < 8; c2++) {
        float mc[8], yc[6];
        #pragma unroll
        for (int r = 0; r < 8; r++)
            mc[r] = __ldg(mbase + (size_t)(r*8 + c2)*64*TS6);
        at6(mc, yc);
        #pragma unroll
        for (int r = 0; r < 6; r++) t2[r][c2] = yc[r];
    }
    float* gbase = &g_winG[((size_t)bc*GP + 6*ty)*GP + 6*tx];
    #pragma unroll
    for (int r = 0; r < 6; r++) {
        float y[6];
        at6(t2[r], y);
        float* gp = gbase + r*GP;
        *(float2*)(gp)     = make_float2(y[0], y[1]);
        *(float2*)(gp + 2) = make_float2(y[2], y[3]);
        *(float2*)(gp + 4) = make_float2(y[4], y[5]);
    }
}

// ---------------------------------------------------------------------------
// Flow-guided bilinear resample of G -> deform conv output. (standalone; the
// R14 fusion into dots regressed ~8us by serializing gathers behind syncs)
__global__ __launch_bounds__(256) void resample_kernel(
    const float* __restrict__ u, const float* __restrict__ v)
{
    int idx = blockIdx.x*256 + threadIdx.x;
    int b = idx >> 16, p = idx & 65535;
    int y = p >> 8, x = p & 255;
    float py  = (float)y + v[b*S + p];
    float px_ = (float)x + u[b*S + p];
    float fy = floorf(py), fx = floorf(px_);
    int y0 = (int)fy, x0 = (int)fx;
    float wy = py - fy, wx = px_ - fx;
    bool r0 = ((unsigned)(y0+1) < (unsigned)GRV);
    bool r1 = ((unsigned)(y0+2) < (unsigned)GRV);
    bool c0 = ((unsigned)(x0+1) < (unsigned)GRV);
    bool c1 = ((unsigned)(x0+2) < (unsigned)GRV);
    int off = (y0+1)*GP + (x0+1);
    float w00 = (1.f-wy)*(1.f-wx), w01 = (1.f-wy)*wx;
    float w10 = wy*(1.f-wx),       w11 = wy*wx;

    const float* Gb = g_winG + (size_t)(b*64)*GP*GP;
    float* dst = &g_conv[(size_t)(b*64)*S + p];
    #pragma unroll 4
    for (int ch = 0; ch < 64; ch++) {
        const float* Gp = Gb + (size_t)ch*GP*GP;
        float g00 = (r0 && c0) ? __ldg(Gp + off)        : 0.f;
        float g01 = (r0 && c1) ? __ldg(Gp + off + 1)    : 0.f;
        float g10 = (r1 && c0) ? __ldg(Gp + off + GP)   : 0.f;
        float g11 = (r1 && c1) ? __ldg(Gp + off + GP+1) : 0.f;
        dst[(size_t)ch*S] = w00*g00 + w01*g01 + w10*g10 + w11*g11;
    }
}

// ---------------------------------------------------------------------------
// Gram + norms (R13 version).
__global__ __launch_bounds__(256) void dots_kernel(const float* __restrict__ xg) {
    __shared__ float qs[16][260];
    __shared__ float ks[16][260];
    __shared__ float s_nq[16], s_nk[16];

    int tid = threadIdx.x;
    int bh  = blockIdx.x >> 5;
    int sl  = blockIdx.x & 31;
    int b   = bh >> 2, hh = bh & 3;
    int i = tid >> 4, j = tid & 15;
    int s0 = sl * 2048;

    if (tid < 16) { s_nq[tid] = 0.f; s_nk[tid] = 0.f; }

    float g = 0.f, nqp = 0.f, nkp = 0.f;
    for (int ch = 0; ch < 8; ++ch) {
        __syncthreads();
        int sbase = s0 + ch*256;
        #pragma unroll
        for (int e = 0; e < 8; ++e) {
            int lin = tid + e*256;
            int r = lin >> 6, c4 = lin & 63;
            const float* src = (r < 16)
                ? (xg     + (size_t)(b*C + hh*HD + r)*S)
                : (g_conv + (size_t)(b*C + hh*HD + (r-16))*S);
            float4 val = *(const float4*)(src + sbase + c4*4);
            float* dst = (r < 16) ? &qs[r][c4*4] : &ks[r-16][c4*4];
            dst[0] = val.x; dst[1] = val.y; dst[2] = val.z; dst[3] = val.w;
        }
        __syncthreads();
        #pragma unroll 8
        for (int s = 0; s < 256; s += 4) {
            float4 qv = *(const float4*)&qs[i][s];
            float4 kv = *(const float4*)&ks[j][s];
            g += qv.x*kv.x; g += qv.y*kv.y; g += qv.z*kv.z; g += qv.w*kv.w;
        }
        #pragma unroll 4
        for (int s = j; s < 256; s += 16) { float q0 = qs[i][s]; nqp += q0*q0; }
        #pragma unroll 4
        for (int s = i; s < 256; s += 16) { float k0 = ks[j][s]; nkp += k0*k0; }
    }
    atomicAdd(&g_gram[bh*256 + i*16 + j], g);
    atomicAdd(&s_nq[i], nqp);
    atomicAdd(&s_nk[j], nkp);
    __syncthreads();
    if (tid < 16)       atomicAdd(&g_qn2[bh*16 + tid], s_nq[tid]);
    else if (tid < 32)  atomicAdd(&g_kn2[bh*16 + tid-16], s_nk[tid-16]);
}

// ---------------------------------------------------------------------------
// Fused softmax + out; float2 columns (16 float2 accs) for occupancy.
__global__ __launch_bounds__(256) void out_kernel(float* __restrict__ out,
                                                  const float* __restrict__ temp) {
    __shared__ float s_attn[16][16];
    int tid = threadIdx.x;
    int bh  = blockIdx.x >> 7;     // 128 tiles of 512 px
    int tile = blockIdx.x & 127;
    int b = bh >> 2, hh = bh & 3;

    {
        int i = tid >> 4, j = tid & 15;
        float dq = fmaxf(sqrtf(g_qn2[bh*16 + i]), 1e-12f);
        float dk = fmaxf(sqrtf(g_kn2[bh*16 + j]), 1e-12f);
        float T  = temp[hh];
        float l  = g_gram[bh*256 + i*16 + j] / (dq*dk) * T;
        float m = l;
        #pragma unroll
        for (int off = 8; off > 0; off >>= 1)
            m = fmaxf(m, __shfl_xor_sync(0xffffffffu, m, off, 16));
        float e = expf(l - m);
        float ssum = e;
        #pragma unroll
        for (int off = 8; off > 0; off >>= 1)
            ssum += __shfl_xor_sync(0xffffffffu, ssum, off, 16);
        s_attn[i][j] = e / ssum;
    }
    __syncthreads();

    int s = tile*512 + tid*2;
    float2 acc[16];
    #pragma unroll
    for (int o = 0; o < 16; o++) acc[o] = make_float2(0.f, 0.f);

    #pragma unroll
    for (int d = 0; d < 16; d++) {
        float2 kvv = *(const float2*)&g_conv[(size_t)(b*C + hh*HD + d)*S + s];
        #pragma unroll
        for (int o = 0; o < 16; o++) {
            float a = s_attn[o][d];
            acc[o].x += a*kvv.x; acc[o].y += a*kvv.y;
        }
    }
    #pragma unroll
    for (int o = 0; o < 16; o++)
        *(float2*)&out[(size_t)(b*C + hh*HD + o)*S + s] = acc[o];
}

// ---------------------------------------------------------------------------
extern "C" void kernel_launch(void* const* d_in, const int* in_sizes, int n_in,
                              void* d_out, int out_size) {
    const float* clone  = (const float*)d_in[0];
    const float* xg     = (const float*)d_in[1];
    const float* u      = (const float*)d_in[2];
    const float* v      = (const float*)d_in[3];
    const float* weight = (const float*)d_in[4];
    const float* temp   = (const float*)d_in[5];
    float* out = (float*)d_out;

    prep_kernel<<<16, 256>>>(weight);
    winograd_in<<<Bn*64*NTYG6, 288>>>(clone);
    winograd_gemm<<<Bn*NF6*NBLK6, 128>>>();
    winograd_out<<<Bn*64*NOB2, 256>>>();
    resample_kernel<<<Bn*S/256, 256>>>(u, v);
    dots_kernel<<<Bn*HEADS*32, 256>>>(xg);
    out_kernel<<<Bn*HEADS*128, 256>>>(out, temp);
}

// round 16
// speedup vs baseline: 1.0597x; 1.0084x over previous
#include <cuda_runtime.h>
#include <math.h>
#include <stdint.h>

#define Bn 2
#define C 64
#define H 256
#define W 256
#define S (H*W)
#define HEADS 4
#define HD 16

#define NT6 43           // F(6x6) tiles per dim: 43*6 = 258 = ext grid exactly
#define NTT6 (NT6*NT6)   // 1849 tiles
#define TS6 1920         // tile stride (15*128)
#define NBLK6 15         // gemm 128-tile blocks per (b,f)
#define NF6 64           // frequencies (8x8)
#define GRV 258          // valid ext-grid rows/cols
#define GP 260           // winG row stride
#define NTYG6 8          // in/out transforms: groups of 6 ty rows (covers 48>=43)

// Scratch (device globals -- no allocations allowed; zero-initialized)
__device__ float g_conv[Bn*C*S];
__device__ float g_gram[Bn*HEADS*HD*HD];
__device__ float g_qn2[Bn*HEADS*HD];
__device__ float g_kn2[Bn*HEADS*HD];
__device__ __align__(16) float g_U[NF6*64*64];       // [f][ci][co]  4MB
__device__ __align__(16) float g_V[Bn*NF6*64*TS6];   // [b][f][ci][t] ~63MB
__device__ __align__(16) float g_M[Bn*NF6*64*TS6];   // [b][f][co][t] ~63MB
__device__ __align__(16) float g_winG[Bn*64*GP*GP];

// ---------------------------------------------------------------------------
// B^T (F(6,3), points 0,±1,±2,±1/2) applied to 8-vector.
__device__ __forceinline__ void bt8(const float* d, float* t) {
    t[0] =  d[0] - 5.25f*d[2] + 5.25f*d[4] - d[6];
    t[1] =  d[1] + d[2] - 4.25f*(d[3] + d[4]) + d[5] + d[6];
    t[2] = -d[1] + d[2] + 4.25f*(d[3] - d[4]) - d[5] + d[6];
    t[3] =  0.5f*d[1] + 0.25f*d[2] - 2.5f*d[3] - 1.25f*d[4] + 2.f*d[5] + d[6];
    t[4] = -0.5f*d[1] + 0.25f*d[2] + 2.5f*d[3] - 1.25f*d[4] - 2.f*d[5] + d[6];
    t[5] =  2.f*d[1] + 4.f*d[2] - 2.5f*d[3] - 5.f*d[4] + 0.5f*d[5] + d[6];
    t[6] = -2.f*d[1] + 4.f*d[2] + 2.5f*d[3] - 5.f*d[4] - 0.5f*d[5] + d[6];
    t[7] = -d[1] + 5.25f*d[3] - 5.25f*d[5] + d[7];
}
// G (8x3) applied to 3-vector.
__device__ __forceinline__ void g8(float g0, float g1, float g2, float* u) {
    u[0] = g0;
    u[1] = (-2.f/9.f)*(g0 + g1 + g2);
    u[2] = (-2.f/9.f)*(g0 - g1 + g2);
    u[3] = (1.f/90.f)*g0 + (1.f/45.f)*g1 + (2.f/45.f)*g2;
    u[4] = (1.f/90.f)*g0 - (1.f/45.f)*g1 + (2.f/45.f)*g2;
    u[5] = (32.f/45.f)*g0 + (16.f/45.f)*g1 + (8.f/45.f)*g2;
    u[6] = (32.f/45.f)*g0 - (16.f/45.f)*g1 + (8.f/45.f)*g2;
    u[7] = g2;
}
// A^T (6x8) applied to 8-vector.
__device__ __forceinline__ void at6(const float* m, float* y) {
    float p12 = m[1]+m[2], m12 = m[1]-m[2];
    float p34 = m[3]+m[4], m34 = m[3]-m[4];
    float p56 = m[5]+m[6], m56 = m[5]-m[6];
    y[0] = m[0] + p12 + p34 + p56;
    y[1] = m12 + 2.f*m34 + 0.5f*m56;
    y[2] = p12 + 4.f*p34 + 0.25f*p56;
    y[3] = m12 + 8.f*m34 + 0.125f*m56;
    y[4] = p12 + 16.f*p34 + 0.0625f*p56;
    y[5] = m12 + 32.f*m34 + 0.03125f*m56 + m[7];
}

// ---------------------------------------------------------------------------
// Prep: U = G g G^T (8x8 per (ci,co)); zero gram accumulators.
__global__ void prep_kernel(const float* __restrict__ weight) {
    int t = blockIdx.x*256 + threadIdx.x;        // 0..4095
    if (t < 4096) {
        int co = t & 63, ci = t >> 6;
        float g[3][3];
        #pragma unroll
        for (int k = 0; k < 9; k++) g[k/3][k%3] = weight[(co*C + ci)*9 + k];
        float q[8][3];
        #pragma unroll
        for (int c = 0; c < 3; c++) {
            float col[8];
            g8(g[0][c], g[1][c], g[2][c], col);
            #pragma unroll
            for (int r = 0; r < 8; r++) q[r][c] = col[r];
        }
        #pragma unroll
        for (int r = 0; r < 8; r++) {
            float ur[8];
            g8(q[r][0], q[r][1], q[r][2], ur);
            #pragma unroll
            for (int c = 0; c < 8; c++)
                g_U[(r*8+c)*4096 + ci*64 + co] = ur[c];
        }
    }
    if (blockIdx.x == 0) {
        int tid = threadIdx.x;
        for (int k = tid; k < Bn*HEADS*HD*HD; k += 256) g_gram[k] = 0.f;
        for (int k = tid; k < Bn*HEADS*HD;    k += 256) { g_qn2[k] = 0.f; g_kn2[k] = 0.f; }
    }
}

// ---------------------------------------------------------------------------
// Input transform: V = B^T d B per 8x8 tile (stride 6, zero-padded clone).
// Block = 288 threads: 258 tasks in ONE round.
__global__ __launch_bounds__(288) void winograd_in(const float* __restrict__ clone) {
    __shared__ float rows[38][256];
    int z   = blockIdx.x;
    int tyg = z % NTYG6;
    int bc  = z / NTYG6;             // b*64 + ci
    int ci  = bc & 63, b = bc >> 6;
    int tid = threadIdx.x;

    const float* plane = clone + ((size_t)bc << 16);
    int gr0 = 36*tyg - 2;
    for (int i = tid; i < 38*64; i += 288) {
        int r = i >> 6, c4 = i & 63;
        int gr = gr0 + r;
        float4 val = make_float4(0.f,0.f,0.f,0.f);
        if ((unsigned)gr < 256u) val = *(const float4*)(plane + gr*256 + c4*4);
        *(float4*)&rows[r][c4*4] = val;
    }
    __syncthreads();

    int task = tid;
    if (task < 6*NT6) {
        int tyl = task / NT6;            // 0..5
        int tx  = task - tyl*NT6;
        int ty  = 6*tyg + tyl;
        if (ty < NT6) {
            float d[8][8];
            int cbase = 6*tx - 2;
            int rl = 6*tyl;
            #pragma unroll
            for (int jj = 0; jj < 8; jj++) {
                int cc = cbase + jj;
                bool ok = ((unsigned)cc < 256u);
                #pragma unroll
                for (int r = 0; r < 8; r++) d[r][jj] = ok ? rows[rl + r][cc] : 0.f;
            }
            float t[8][8];
            #pragma unroll
            for (int c2 = 0; c2 < 8; c2++) {
                float dc[8], tc[8];
                #pragma unroll
                for (int r = 0; r < 8; r++) dc[r] = d[r][c2];
                bt8(dc, tc);
                #pragma unroll
                for (int r = 0; r < 8; r++) t[r][c2] = tc[r];
            }
            int tlin = ty*NT6 + tx;
            #pragma unroll
            for (int r = 0; r < 8; r++) {
                float vr[8];
                bt8(t[r], vr);
                #pragma unroll
                for (int c2 = 0; c2 < 8; c2++)
                    g_V[((b*NF6 + r*8+c2)*64 + ci)*TS6 + tlin] = vr[c2];
            }
        }
    }
}

// ---------------------------------------------------------------------------
// Per-frequency GEMM, single-stage full-K smem, 8co x 8t thread tile.
__global__ __launch_bounds__(128, 3) void winograd_gemm() {
    __shared__ float Vs[64][128];    // 32 KB
    __shared__ float Us[64][64];     // 16 KB
    int bf = blockIdx.x / NBLK6;     // b*64 + f
    int tc = blockIdx.x % NBLK6;
    int f  = bf & 63;
    int t0 = tc * 128;
    int tid = threadIdx.x;
    int cg = tid >> 4, tg = tid & 15;

    {
        const float* vsrc = &g_V[(size_t)(bf*64)*TS6 + t0];
        #pragma unroll
        for (int i = 0; i < 16; i++) {
            int lin = tid + i*128;
            int r = lin >> 5, c = lin & 31;
            *(float4*)&Vs[r][c*4] = *(const float4*)(vsrc + (size_t)r*TS6 + c*4);
        }
        const float* usrc = &g_U[f*4096];
        #pragma unroll
        for (int i = 0; i < 8; i++) {
            int lin = tid + i*128;
            int r = lin >> 4, c = lin & 15;
            *(float4*)&Us[r][c*4] = *(const float4*)(usrc + r*64 + c*4);
        }
    }
    __syncthreads();

    float acc[8][8];
    #pragma unroll
    for (int i = 0; i < 8; i++)
        #pragma unroll
        for (int j = 0; j < 8; j++) acc[i][j] = 0.f;

    #pragma unroll 4
    for (int cl = 0; cl < 64; cl++) {
        float4 w0 = *(const float4*)&Us[cl][cg*8];
        float4 w1 = *(const float4*)&Us[cl][cg*8 + 4];
        float4 s0 = *(const float4*)&Vs[cl][tg*8];
        float4 s1 = *(const float4*)&Vs[cl][tg*8 + 4];
        float wv[8] = {w0.x, w0.y, w0.z, w0.w, w1.x, w1.y, w1.z, w1.w};
        float sv[8] = {s0.x, s0.y, s0.z, s0.w, s1.x, s1.y, s1.z, s1.w};
        #pragma unroll
        for (int i = 0; i < 8; i++)
            #pragma unroll
            for (int j = 0; j < 8; j++)
                acc[i][j] += wv[i]*sv[j];
    }

    #pragma unroll
    for (int i = 0; i < 8; i++) {
        float* mp = &g_M[(size_t)(bf*64 + cg*8 + i)*TS6 + t0 + tg*8];
        *(float4*)mp       = make_float4(acc[i][0], acc[i][1], acc[i][2], acc[i][3]);
        *(float4*)(mp + 4) = make_float4(acc[i][4], acc[i][5], acc[i][6], acc[i][7]);
    }
}

// ---------------------------------------------------------------------------
// Output transform: Y = A^T m A (6x6 outputs). Column-streamed loads +
// SMEM-STAGED COALESCED STORES (R15 showed L1 51% = strided STG wavefronts).
// Block = (b*64+co, 6-ty-row group), 288 threads, 258 transform tasks, then
// stream 36 winG rows out as aligned float4s (padding cols never read).
__global__ __launch_bounds__(288) void winograd_out() {
    __shared__ float ys[36][260];
    int z   = blockIdx.x;
    int tyg = z % NTYG6;
    int bc  = z / NTYG6;             // b*64 + co
    int co  = bc & 63, b = bc >> 6;
    int tid = threadIdx.x;

    int task = tid;
    if (task < 6*NT6) {
        int tyl = task / NT6;            // 0..5
        int tx  = task - tyl*NT6;
        int ty  = 6*tyg + tyl;
        if (ty < NT6) {
            int tlin = ty*NT6 + tx;
            const float* mbase = &g_M[(size_t)(b*NF6*64 + co)*TS6 + tlin];
            float t2[6][8];
            #pragma unroll
            for (int c2 = 0; c2 < 8; c2++) {
                float mc[8], yc[6];
                #pragma unroll
                for (int r = 0; r < 8; r++)
                    mc[r] = __ldg(mbase + (size_t)(r*8 + c2)*64*TS6);
                at6(mc, yc);
                #pragma unroll
                for (int r = 0; r < 6; r++) t2[r][c2] = yc[r];
            }
            #pragma unroll
            for (int r = 0; r < 6; r++) {
                float y[6];
                at6(t2[r], y);
                float* yp = &ys[tyl*6 + r][6*tx];
                yp[0] = y[0]; yp[1] = y[1]; yp[2] = y[2];
                yp[3] = y[3]; yp[4] = y[4]; yp[5] = y[5];
            }
        }
    }
    __syncthreads();

    int gr0 = 36*tyg;
    int nrows = min(36, GRV - gr0);      // last group: 6 rows
    float* gdst = &g_winG[((size_t)bc*GP + gr0)*GP];
    for (int i = tid; i < nrows*65; i += 288) {
        int r = i / 65, c = i - r*65;
        *(float4*)(gdst + (size_t)r*GP + c*4) = *(const float4*)&ys[r][c*4];
    }
}

// ---------------------------------------------------------------------------
// Flow-guided bilinear resample of G -> deform conv output.
__global__ __launch_bounds__(256) void resample_kernel(
    const float* __restrict__ u, const float* __restrict__ v)
{
    int idx = blockIdx.x*256 + threadIdx.x;
    int b = idx >> 16, p = idx & 65535;
    int y = p >> 8, x = p & 255;
    float py  = (float)y + v[b*S + p];
    float px_ = (float)x + u[b*S + p];
    float fy = floorf(py), fx = floorf(px_);
    int y0 = (int)fy, x0 = (int)fx;
    float wy = py - fy, wx = px_ - fx;
    bool r0 = ((unsigned)(y0+1) < (unsigned)GRV);
    bool r1 = ((unsigned)(y0+2) < (unsigned)GRV);
    bool c0 = ((unsigned)(x0+1) < (unsigned)GRV);
    bool c1 = ((unsigned)(x0+2) < (unsigned)GRV);
    int off = (y0+1)*GP + (x0+1);
    float w00 = (1.f-wy)*(1.f-wx), w01 = (1.f-wy)*wx;
    float w10 = wy*(1.f-wx),       w11 = wy*wx;

    const float* Gb = g_winG + (size_t)(b*64)*GP*GP;
    float* dst = &g_conv[(size_t)(b*64)*S + p];
    #pragma unroll 4
    for (int ch = 0; ch < 64; ch++) {
        const float* Gp = Gb + (size_t)ch*GP*GP;
        float g00 = (r0 && c0) ? __ldg(Gp + off)        : 0.f;
        float g01 = (r0 && c1) ? __ldg(Gp + off + 1)    : 0.f;
        float g10 = (r1 && c0) ? __ldg(Gp + off + GP)   : 0.f;
        float g11 = (r1 && c1) ? __ldg(Gp + off + GP+1) : 0.f;
        dst[(size_t)ch*S] = w00*g00 + w01*g01 + w10*g10 + w11*g11;
    }
}

// ---------------------------------------------------------------------------
// Gram + norms.
__global__ __launch_bounds__(256) void dots_kernel(const float* __restrict__ xg) {
    __shared__ float qs[16][260];
    __shared__ float ks[16][260];
    __shared__ float s_nq[16], s_nk[16];

    int tid = threadIdx.x;
    int bh  = blockIdx.x >> 5;
    int sl  = blockIdx.x & 31;
    int b   = bh >> 2, hh = bh & 3;
    int i = tid >> 4, j = tid & 15;
    int s0 = sl * 2048;

    if (tid < 16) { s_nq[tid] = 0.f; s_nk[tid] = 0.f; }

    float g = 0.f, nqp = 0.f, nkp = 0.f;
    for (int ch = 0; ch < 8; ++ch) {
        __syncthreads();
        int sbase = s0 + ch*256;
        #pragma unroll
        for (int e = 0; e < 8; ++e) {
            int lin = tid + e*256;
            int r = lin >> 6, c4 = lin & 63;
            const float* src = (r < 16)
                ? (xg     + (size_t)(b*C + hh*HD + r)*S)
                : (g_conv + (size_t)(b*C + hh*HD + (r-16))*S);
            float4 val = *(const float4*)(src + sbase + c4*4);
            float* dst = (r < 16) ? &qs[r][c4*4] : &ks[r-16][c4*4];
            dst[0] = val.x; dst[1] = val.y; dst[2] = val.z; dst[3] = val.w;
        }
        __syncthreads();
        #pragma unroll 8
        for (int s = 0; s < 256; s += 4) {
            float4 qv = *(const float4*)&qs[i][s];
            float4 kv = *(const float4*)&ks[j][s];
            g += qv.x*kv.x; g += qv.y*kv.y; g += qv.z*kv.z; g += qv.w*kv.w;
        }
        #pragma unroll 4
        for (int s = j; s < 256; s += 16) { float q0 = qs[i][s]; nqp += q0*q0; }
        #pragma unroll 4
        for (int s = i; s < 256; s += 16) { float k0 = ks[j][s]; nkp += k0*k0; }
    }
    atomicAdd(&g_gram[bh*256 + i*16 + j], g);
    atomicAdd(&s_nq[i], nqp);
    atomicAdd(&s_nk[j], nkp);
    __syncthreads();
    if (tid < 16)       atomicAdd(&g_qn2[bh*16 + tid], s_nq[tid]);
    else if (tid < 32)  atomicAdd(&g_kn2[bh*16 + tid-16], s_nk[tid-16]);
}

// ---------------------------------------------------------------------------
// Fused softmax + out; float2 columns (16 float2 accs) for occupancy.
__global__ __launch_bounds__(256) void out_kernel(float* __restrict__ out,
                                                  const float* __restrict__ temp) {
    __shared__ float s_attn[16][16];
    int tid = threadIdx.x;
    int bh  = blockIdx.x >> 7;     // 128 tiles of 512 px
    int tile = blockIdx.x & 127;
    int b = bh >> 2, hh = bh & 3;

    {
        int i = tid >> 4, j = tid & 15;
        float dq = fmaxf(sqrtf(g_qn2[bh*16 + i]), 1e-12f);
        float dk = fmaxf(sqrtf(g_kn2[bh*16 + j]), 1e-12f);
        float T  = temp[hh];
        float l  = g_gram[bh*256 + i*16 + j] / (dq*dk) * T;
        float m = l;
        #pragma unroll
        for (int off = 8; off > 0; off >>= 1)
            m = fmaxf(m, __shfl_xor_sync(0xffffffffu, m, off, 16));
        float e = expf(l - m);
        float ssum = e;
        #pragma unroll
        for (int off = 8; off > 0; off >>= 1)
            ssum += __shfl_xor_sync(0xffffffffu, ssum, off, 16);
        s_attn[i][j] = e / ssum;
    }
    __syncthreads();

    int s = tile*512 + tid*2;
    float2 acc[16];
    #pragma unroll
    for (int o = 0; o < 16; o++) acc[o] = make_float2(0.f, 0.f);

    #pragma unroll
    for (int d = 0; d < 16; d++) {
        float2 kvv = *(const float2*)&g_conv[(size_t)(b*C + hh*HD + d)*S + s];
        #pragma unroll
        for (int o = 0; o < 16; o++) {
            float a = s_attn[o][d];
            acc[o].x += a*kvv.x; acc[o].y += a*kvv.y;
        }
    }
    #pragma unroll
    for (int o = 0; o < 16; o++)
        *(float2*)&out[(size_t)(b*C + hh*HD + o)*S + s] = acc[o];
}

// ---------------------------------------------------------------------------
extern "C" void kernel_launch(void* const* d_in, const int* in_sizes, int n_in,
                              void* d_out, int out_size) {
    const float* clone  = (const float*)d_in[0];
    const float* xg     = (const float*)d_in[1];
    const float* u      = (const float*)d_in[2];
    const float* v      = (const float*)d_in[3];
    const float* weight = (const float*)d_in[4];
    const float* temp   = (const float*)d_in[5];
    float* out = (float*)d_out;

    prep_kernel<<<16, 256>>>(weight);
    winograd_in<<<Bn*64*NTYG6, 288>>>(clone);
    winograd_gemm<<<Bn*NF6*NBLK6, 128>>>();
    winograd_out<<<Bn*64*NTYG6, 288>>>();
    resample_kernel<<<Bn*S/256, 256>>>(u, v);
    dots_kernel<<<Bn*HEADS*32, 256>>>(xg);
    out_kernel<<<Bn*HEADS*128, 256>>>(out, temp);
}